// round 8
// baseline (speedup 1.0000x reference)
#include <cuda_runtime.h>
#include <cuda_fp16.h>
#include <math.h>
#include <stdint.h>

// ---------------------------------------------------------------------------
// AIO_DownsampleCouplingBlock — Round 7: fp16 mma.sync m16n8k16 (same 11-bit
// significand as tf32 => same accuracy), NHWC half inputs, 4-stage cp.async.
// ---------------------------------------------------------------------------

__device__ float g_a[32 * 384 * 1024];                  // a1 / a2 (f32)
__device__ __align__(16) __half g_xh[32 * 64 * 64 * 48];    // x1 NHWC half
__device__ __align__(16) __half g_y2h[32 * 32 * 32 * 192];  // y2 NHWC half
__device__ __align__(16) __half g_wp1[18 * 384 * 32];       // conv1 w [st][n][k]
__device__ __align__(16) __half g_wp2[54 * 384 * 32];       // conv2 w [st][n][k]
__device__ int   g_invperm[384];
__device__ float g_scale[384];

__device__ __forceinline__ void cp_async16(unsigned dst, const void* src) {
    asm volatile("cp.async.cg.shared.global [%0], [%1], 16;\n"
                 :: "r"(dst), "l"(src));
}
__device__ __forceinline__ void cp_async16z(unsigned dst, const void* src, int sz) {
    asm volatile("cp.async.cg.shared.global [%0], [%1], 16, %2;\n"
                 :: "r"(dst), "l"(src), "r"(sz));
}

// ---------------------------------------------------------------------------
__global__ void prep_kernel(const float* __restrict__ perm_w,
                            const float* __restrict__ act_norm) {
    int p = threadIdx.x;
    if (p < 384) {
        int o_found = 0;
        for (int o = 0; o < 384; ++o)
            if (perm_w[o * 384 + p] > 0.5f) o_found = o;
        g_invperm[p] = o_found;
        g_scale[p] = 0.2f * log1pf(expf(0.5f * act_norm[p]));
    }
}

// pack OIHW w[n,c,kh,kw] -> dst[st][n(384)][k(32)] half, st = tap*CH + cblk
__global__ void pack_kernel(const float* __restrict__ w, int cin, int CH, int which) {
    __half* dst = which ? ((__half*)g_wp2) : ((__half*)g_wp1);
    int idx = blockIdx.x * 256 + threadIdx.x;
    int total = 9 * CH * 384 * 32;
    if (idx >= total) return;
    int k = idx & 31;
    int n = (idx >> 5) % 384;
    int st = idx / (384 * 32);
    int tap = st / CH;
    int c = (st % CH) * 32 + k;
    float v = (c < cin) ? w[(n * cin + c) * 9 + tap] : 0.0f;
    dst[idx] = __float2half(v);
}

// x (NCHW f32, first 48 channels) -> g_xh (NHWC half)
__global__ __launch_bounds__(256) void x2h_kernel(const float* __restrict__ x) {
    __shared__ float tile[48][65];
    const int b = blockIdx.x >> 6, h = blockIdx.x & 63;
    for (int idx = threadIdx.x; idx < 48 * 64; idx += 256) {
        const int c = idx >> 6, w = idx & 63;
        tile[c][w] = x[(((size_t)b * 96 + c) * 64 + h) * 64 + w];
    }
    __syncthreads();
    for (int idx = threadIdx.x; idx < 64 * 48; idx += 256) {
        const int w = idx / 48, c = idx % 48;
        g_xh[(((size_t)b * 64 + h) * 64 + w) * 48 + c] = __float2half(tile[c][w]);
    }
}

// ---------------------------------------------------------------------------
// implicit-GEMM conv, fp16 m16n8k16 mma.sync, 4-stage cp.async, BK=32
// M=32768 px, N=384 (3 blocks x 128), K=CINP*9.
// A smem [m(128)][k(32h)] rows padded to 80B; B smem [n(128)][k(32h)] 80B rows.
// 256 thr / 8 warps, warp grid 2(M) x 4(N), warp tile 64x32, 64 f32 acc/thread
// ---------------------------------------------------------------------------
#define ASTG 10240          // 128*80 bytes
#define STGB 20480          // A + B per stage

template <int CIN, int CINP, int STRIDE, int HIN, int CTOT, int WHICH>
__global__ __launch_bounds__(256, 2) void conv_gemm(const float* __restrict__ bias) {
    extern __shared__ __align__(16) char smem[];

    const __half* inp = (WHICH == 1) ? (const __half*)g_xh : (const __half*)g_y2h;
    const __half* wp  = (WHICH == 1) ? (const __half*)g_wp1 : (const __half*)g_wp2;

    const int tid  = threadIdx.x;
    const int lane = tid & 31;
    const int warp = tid >> 5;
    const int wm = warp >> 2;
    const int wn = warp & 3;
    const int g4 = lane >> 2;
    const int t4 = lane & 3;

    const int bm   = blockIdx.x;
    const int bimg = bm >> 3;
    const int h0   = (bm & 7) * 4;
    const int n0   = blockIdx.y * 128;

    constexpr int CH  = CINP / 32;
    constexpr int NIT = 9 * CH;

    float acc[4][4][4];
#pragma unroll
    for (int i = 0; i < 4; i++)
#pragma unroll
        for (int j = 0; j < 4; j++)
#pragma unroll
            for (int k = 0; k < 4; k++) acc[i][j][k] = 0.f;

    auto load_stage = [&](int it, int s) {
        const int tap = it / CH;
        const int c0  = (it - tap * CH) * 32;
        const int dh = tap / 3 - 1;
        const int dw = tap % 3 - 1;
        const unsigned aB = (unsigned)__cvta_generic_to_shared(smem + s * STGB);
        const unsigned bB = aB + ASTG;
        // A: 128 rows x 4 chunks of 16B (8 halves = 8 channels), NHWC source
#pragma unroll
        for (int p = 0; p < 2; ++p) {
            const int task = tid + 256 * p;
            const int row = task >> 2;
            const int ch  = task & 3;
            const int h = h0 + (row >> 5);
            const int w = row & 31;
            const int ih = h * STRIDE + dh;
            const int iw = w * STRIDE + dw;
            const bool ok = (ih >= 0) && (ih < HIN) && (iw >= 0) && (iw < HIN)
                            && (c0 + ch * 8 < CIN);
            const __half* src = ok
                ? inp + ((size_t)(bimg * HIN + ih) * HIN + iw) * CTOT + c0 + ch * 8
                : inp;
            cp_async16z(aB + (unsigned)(row * 80 + ch * 16), src, ok ? 16 : 0);
        }
        // B: 128 n-rows x 4 chunks of 16B from packed [st][n][k]
        const __half* wsrc = wp + (size_t)it * (384 * 32) + (size_t)n0 * 32;
#pragma unroll
        for (int p = 0; p < 2; ++p) {
            const int task = tid + 256 * p;
            const int row = task >> 2;
            const int ch  = task & 3;
            cp_async16(bB + (unsigned)(row * 80 + ch * 16), wsrc + row * 32 + ch * 8);
        }
    };

    load_stage(0, 0);
    asm volatile("cp.async.commit_group;\n" ::: "memory");
    load_stage(1, 1);
    asm volatile("cp.async.commit_group;\n" ::: "memory");
    load_stage(2, 2);
    asm volatile("cp.async.commit_group;\n" ::: "memory");

#pragma unroll 1
    for (int it = 0; it < NIT; ++it) {
        const int s = it & 3;
        if (it + 3 < NIT) {
            load_stage(it + 3, (it + 3) & 3);
            asm volatile("cp.async.commit_group;\n" ::: "memory");
            asm volatile("cp.async.wait_group 3;\n" ::: "memory");
        } else if (it + 3 == NIT) {
            asm volatile("cp.async.wait_group 2;\n" ::: "memory");
        } else if (it + 2 == NIT) {
            asm volatile("cp.async.wait_group 1;\n" ::: "memory");
        } else {
            asm volatile("cp.async.wait_group 0;\n" ::: "memory");
        }
        __syncthreads();

        const char* Ak = smem + s * STGB;
        const char* Bk = Ak + ASTG;
#pragma unroll
        for (int step = 0; step < 2; ++step) {
            const int kb = step * 32;   // byte offset of k16 block within 64B row
            uint32_t af[4][4];
#pragma unroll
            for (int mi = 0; mi < 4; ++mi) {
                const int r = wm * 64 + mi * 16 + g4;
                af[mi][0] = *(const uint32_t*)(Ak + r * 80 + kb + 4 * t4);
                af[mi][1] = *(const uint32_t*)(Ak + (r + 8) * 80 + kb + 4 * t4);
                af[mi][2] = *(const uint32_t*)(Ak + r * 80 + kb + 16 + 4 * t4);
                af[mi][3] = *(const uint32_t*)(Ak + (r + 8) * 80 + kb + 16 + 4 * t4);
            }
            uint32_t bf[4][2];
#pragma unroll
            for (int ni = 0; ni < 4; ++ni) {
                const int n = wn * 32 + ni * 8 + g4;
                bf[ni][0] = *(const uint32_t*)(Bk + n * 80 + kb + 4 * t4);
                bf[ni][1] = *(const uint32_t*)(Bk + n * 80 + kb + 16 + 4 * t4);
            }
#pragma unroll
            for (int mi = 0; mi < 4; ++mi)
#pragma unroll
                for (int ni = 0; ni < 4; ++ni) {
                    asm volatile(
                        "mma.sync.aligned.m16n8k16.row.col.f32.f16.f16.f32 "
                        "{%0,%1,%2,%3}, {%4,%5,%6,%7}, {%8,%9}, {%0,%1,%2,%3};"
                        : "+f"(acc[mi][ni][0]), "+f"(acc[mi][ni][1]),
                          "+f"(acc[mi][ni][2]), "+f"(acc[mi][ni][3])
                        : "r"(af[mi][0]), "r"(af[mi][1]),
                          "r"(af[mi][2]), "r"(af[mi][3]),
                          "r"(bf[ni][0]), "r"(bf[ni][1]));
                }
        }
        __syncthreads();
    }

    // epilogue: add bias, store NCHW f32 to g_a
#pragma unroll
    for (int mi = 0; mi < 4; ++mi) {
#pragma unroll
        for (int ni = 0; ni < 4; ++ni) {
            const int n = n0 + wn * 32 + ni * 8 + 2 * t4;
            const float b0v = bias[n];
            const float b1v = bias[n + 1];
#pragma unroll
            for (int rr = 0; rr < 2; ++rr) {
                const int m = wm * 64 + mi * 16 + g4 + rr * 8;
                const int h = h0 + (m >> 5);
                const int w = m & 31;
                size_t base = ((size_t)(bimg * 384 + n) * 32 + h) * 32 + w;
                g_a[base]        = acc[mi][ni][rr * 2 + 0] + b0v;
                g_a[base + 1024] = acc[mi][ni][rr * 2 + 1] + b1v;
            }
        }
    }
}

// ---------------------------------------------------------------------------
// affine1: block per (b,h). Computes y2, writes out rows perm(192+c) (f32),
// and stages y2 -> NHWC half for conv2's A path.
// ---------------------------------------------------------------------------
__global__ __launch_bounds__(256) void affine1_kernel(const float* __restrict__ x,
                                                      const float* __restrict__ act_offset,
                                                      float* __restrict__ outp) {
    __shared__ __half yt[32][194];
    const int b = blockIdx.x >> 5, h = blockIdx.x & 31;

    for (int idx = threadIdx.x; idx < 192 * 32; idx += 256) {
        const int c = idx >> 5, w = idx & 31;
        const int hw = h * 32 + w;
        const float lo = g_a[(((size_t)(b * 384 + c)) << 10) + hw];
        const float hi = g_a[(((size_t)(b * 384 + c + 192)) << 10) + hw];
        const int cc = c >> 2, ii = (c >> 1) & 1, jj = c & 1;
        const float xd = x[(((size_t)b * 96 + 48 + cc) * 64 + 2 * h + ii) * 64 + 2 * w + jj];
        const float y = xd * expf(2.0f * tanhf(0.2f * lo)) + hi;
        yt[w][c] = __float2half(y);
        const int p = 192 + c;
        outp[(((size_t)(b * 384 + g_invperm[p])) << 10) + hw] = y * g_scale[p] + act_offset[p];
    }
    __syncthreads();
    for (int idx = threadIdx.x; idx < 32 * 96; idx += 256) {
        const int w = idx / 96;
        const int c2 = (idx % 96) * 2;
        *(__half2*)&g_y2h[(((size_t)(b * 32 + h) * 32) + w) * 192 + c2] =
            *(const __half2*)&yt[w][c2];
    }
}

// affine2: y1 from down(x1)+a2 -> out rows perm(c)  (unchanged hw mapping)
__global__ __launch_bounds__(256) void affine2_kernel(const float* __restrict__ x,
                                                      const float* __restrict__ act_offset,
                                                      float* __restrict__ outp) {
    int idx = blockIdx.x * 256 + threadIdx.x;
    if (idx >= 32 * 96 * 1024) return;
    const int hw = idx & 1023;
    const int t = idx >> 10;
    const int cp = t % 96;
    const int b = t / 96;
    const int h = hw >> 5, w = hw & 31;
    const int c0 = 2 * cp;
    const int cc = cp >> 1, ii = cp & 1;

    const float lo0 = g_a[(((size_t)(b * 384 + c0)) << 10) + hw];
    const float lo1 = g_a[(((size_t)(b * 384 + c0 + 1)) << 10) + hw];
    const float hi0 = g_a[(((size_t)(b * 384 + c0 + 192)) << 10) + hw];
    const float hi1 = g_a[(((size_t)(b * 384 + c0 + 193)) << 10) + hw];
    const float2 xd = *(const float2*)&x[(((size_t)b * 96 + cc) * 64 + 2 * h + ii) * 64 + 2 * w];

    const float y0 = xd.x * expf(2.0f * tanhf(0.2f * lo0)) + hi0;
    const float y1 = xd.y * expf(2.0f * tanhf(0.2f * lo1)) + hi1;

    outp[(((size_t)(b * 384 + g_invperm[c0])) << 10) + hw]     = y0 * g_scale[c0] + act_offset[c0];
    outp[(((size_t)(b * 384 + g_invperm[c0 + 1])) << 10) + hw] = y1 * g_scale[c0 + 1] + act_offset[c0 + 1];
}

// ---------------------------------------------------------------------------
extern "C" void kernel_launch(void* const* d_in, const int* in_sizes, int n_in,
                              void* d_out, int out_size) {
    const float* x          = (const float*)d_in[0];
    const float* w_hi       = (const float*)d_in[1];
    const float* b_hi       = (const float*)d_in[2];
    const float* w_lo       = (const float*)d_in[3];
    const float* b_lo       = (const float*)d_in[4];
    const float* act_norm   = (const float*)d_in[5];
    const float* act_offset = (const float*)d_in[6];
    const float* perm_w     = (const float*)d_in[7];
    float* out = (float*)d_out;

    const int SMEM_DYN = 4 * STGB;   // 81920 B

    cudaFuncSetAttribute(conv_gemm<48, 64, 2, 64, 48, 1>,
                         cudaFuncAttributeMaxDynamicSharedMemorySize, SMEM_DYN);
    cudaFuncSetAttribute(conv_gemm<192, 192, 1, 32, 192, 2>,
                         cudaFuncAttributeMaxDynamicSharedMemorySize, SMEM_DYN);

    prep_kernel<<<1, 384>>>(perm_w, act_norm);
    pack_kernel<<<(9 * 2 * 384 * 32 + 255) / 256, 256>>>(w_hi, 48, 2, 0);
    pack_kernel<<<(9 * 6 * 384 * 32 + 255) / 256, 256>>>(w_lo, 192, 6, 1);
    x2h_kernel<<<32 * 64, 256>>>(x);

    conv_gemm<48, 64, 2, 64, 48, 1><<<dim3(256, 3), 256, SMEM_DYN>>>(b_hi);

    affine1_kernel<<<32 * 32, 256>>>(x, act_offset, out);

    conv_gemm<192, 192, 1, 32, 192, 2><<<dim3(256, 3), 256, SMEM_DYN>>>(b_lo);

    {
        int total = 32 * 96 * 1024;
        affine2_kernel<<<(total + 255) / 256, 256>>>(x, act_offset, out);
    }
}

// round 9
// speedup vs baseline: 1.6871x; 1.6871x over previous
#include <cuda_runtime.h>
#include <cuda_fp16.h>
#include <math.h>
#include <stdint.h>

// ---------------------------------------------------------------------------
// AIO_DownsampleCouplingBlock — Round 9: fp16 m16n8k16 + ldmatrix fragment
// loads + single-barrier 4-stage cp.async pipeline.
// ---------------------------------------------------------------------------

__device__ float g_a[32 * 384 * 1024];                  // a1 / a2 (f32)
__device__ __align__(16) __half g_xh[32 * 64 * 64 * 48];    // x1 NHWC half
__device__ __align__(16) __half g_y2h[32 * 32 * 32 * 192];  // y2 NHWC half
__device__ __align__(16) __half g_wp1[18 * 384 * 32];       // conv1 w [st][n][k]
__device__ __align__(16) __half g_wp2[54 * 384 * 32];       // conv2 w [st][n][k]
__device__ int   g_invperm[384];
__device__ float g_scale[384];

__device__ __forceinline__ void cp_async16(unsigned dst, const void* src) {
    asm volatile("cp.async.cg.shared.global [%0], [%1], 16;\n"
                 :: "r"(dst), "l"(src));
}
__device__ __forceinline__ void cp_async16z(unsigned dst, const void* src, int sz) {
    asm volatile("cp.async.cg.shared.global [%0], [%1], 16, %2;\n"
                 :: "r"(dst), "l"(src), "r"(sz));
}
__device__ __forceinline__ void ldsm4(uint32_t& r0, uint32_t& r1,
                                      uint32_t& r2, uint32_t& r3, unsigned addr) {
    asm volatile("ldmatrix.sync.aligned.m8n8.x4.shared.b16 {%0,%1,%2,%3}, [%4];"
                 : "=r"(r0), "=r"(r1), "=r"(r2), "=r"(r3) : "r"(addr));
}

// ---------------------------------------------------------------------------
__global__ void prep_kernel(const float* __restrict__ perm_w,
                            const float* __restrict__ act_norm) {
    int p = threadIdx.x;
    if (p < 384) {
        int o_found = 0;
        for (int o = 0; o < 384; ++o)
            if (perm_w[o * 384 + p] > 0.5f) o_found = o;
        g_invperm[p] = o_found;
        g_scale[p] = 0.2f * log1pf(expf(0.5f * act_norm[p]));
    }
}

// pack OIHW w[n,c,kh,kw] -> dst[st][n(384)][k(32)] half, st = tap*CH + cblk
__global__ void pack_kernel(const float* __restrict__ w, int cin, int CH, int which) {
    __half* dst = which ? ((__half*)g_wp2) : ((__half*)g_wp1);
    int idx = blockIdx.x * 256 + threadIdx.x;
    int total = 9 * CH * 384 * 32;
    if (idx >= total) return;
    int k = idx & 31;
    int n = (idx >> 5) % 384;
    int st = idx / (384 * 32);
    int tap = st / CH;
    int c = (st % CH) * 32 + k;
    float v = (c < cin) ? w[(n * cin + c) * 9 + tap] : 0.0f;
    dst[idx] = __float2half(v);
}

// x (NCHW f32, first 48 channels) -> g_xh (NHWC half), half2 stores
__global__ __launch_bounds__(256) void x2h_kernel(const float* __restrict__ x) {
    __shared__ float tile[48][65];
    const int b = blockIdx.x >> 6, h = blockIdx.x & 63;
    for (int idx = threadIdx.x; idx < 48 * 64; idx += 256) {
        const int c = idx >> 6, w = idx & 63;
        tile[c][w] = x[(((size_t)b * 96 + c) * 64 + h) * 64 + w];
    }
    __syncthreads();
    for (int idx = threadIdx.x; idx < 64 * 24; idx += 256) {
        const int w = idx / 24, cp = idx % 24;
        __half2 v = __floats2half2_rn(tile[2 * cp][w], tile[2 * cp + 1][w]);
        *(__half2*)&g_xh[(((size_t)b * 64 + h) * 64 + w) * 48 + 2 * cp] = v;
    }
}

// ---------------------------------------------------------------------------
// implicit-GEMM conv, fp16 m16n8k16 mma.sync + ldmatrix, 4-stage cp.async,
// single __syncthreads per iteration.  BK=32, M=32768 px, N=384 (3 x 128).
// A smem [m(128)][k(32h)] 80B rows; B smem [n(128)][k(32h)] 80B rows.
// ---------------------------------------------------------------------------
#define ASTG 10240          // 128*80 bytes
#define STGB 20480          // A + B per stage

template <int CIN, int CINP, int STRIDE, int HIN, int CTOT, int WHICH>
__global__ __launch_bounds__(256, 2) void conv_gemm(const float* __restrict__ bias) {
    extern __shared__ __align__(16) char smem[];

    const __half* inp = (WHICH == 1) ? (const __half*)g_xh : (const __half*)g_y2h;
    const __half* wp  = (WHICH == 1) ? (const __half*)g_wp1 : (const __half*)g_wp2;

    const int tid  = threadIdx.x;
    const int lane = tid & 31;
    const int warp = tid >> 5;
    const int wm = warp >> 2;
    const int wn = warp & 3;
    const int g4 = lane >> 2;
    const int t4 = lane & 3;

    const int bm   = blockIdx.x;
    const int bimg = bm >> 3;
    const int h0   = (bm & 7) * 4;
    const int n0   = blockIdx.y * 128;

    constexpr int CH  = CINP / 32;
    constexpr int NIT = 9 * CH;

    const unsigned smemBase = (unsigned)__cvta_generic_to_shared(smem);
    // ldmatrix lane-address components (constant across iterations)
    const int aRowL = wm * 64 + (lane & 15);          // + mi*16
    const int aKoffL = (lane >> 4) << 4;              // + kb
    const int bRowL = wn * 32 + ((lane >> 4) << 3) + (lane & 7);   // + ni2*16
    const int bKoffL = ((lane >> 3) & 1) << 4;        // + kb

    float acc[4][4][4];
#pragma unroll
    for (int i = 0; i < 4; i++)
#pragma unroll
        for (int j = 0; j < 4; j++)
#pragma unroll
            for (int k = 0; k < 4; k++) acc[i][j][k] = 0.f;

    auto load_stage = [&](int it, int s) {
        const int tap = it / CH;
        const int c0  = (it - tap * CH) * 32;
        const int dh = tap / 3 - 1;
        const int dw = tap % 3 - 1;
        const unsigned aB = smemBase + s * STGB;
        const unsigned bB = aB + ASTG;
#pragma unroll
        for (int p = 0; p < 2; ++p) {
            const int task = tid + 256 * p;
            const int row = task >> 2;
            const int ch  = task & 3;
            const int h = h0 + (row >> 5);
            const int w = row & 31;
            const int ih = h * STRIDE + dh;
            const int iw = w * STRIDE + dw;
            const bool ok = (ih >= 0) && (ih < HIN) && (iw >= 0) && (iw < HIN)
                            && (c0 + ch * 8 < CIN);
            const __half* src = ok
                ? inp + ((size_t)(bimg * HIN + ih) * HIN + iw) * CTOT + c0 + ch * 8
                : inp;
            cp_async16z(aB + (unsigned)(row * 80 + ch * 16), src, ok ? 16 : 0);
        }
        const __half* wsrc = wp + (size_t)it * (384 * 32) + (size_t)n0 * 32;
#pragma unroll
        for (int p = 0; p < 2; ++p) {
            const int task = tid + 256 * p;
            const int row = task >> 2;
            const int ch  = task & 3;
            cp_async16(bB + (unsigned)(row * 80 + ch * 16), wsrc + row * 32 + ch * 8);
        }
    };

    load_stage(0, 0);
    asm volatile("cp.async.commit_group;\n" ::: "memory");
    load_stage(1, 1);
    asm volatile("cp.async.commit_group;\n" ::: "memory");
    load_stage(2, 2);
    asm volatile("cp.async.commit_group;\n" ::: "memory");

#pragma unroll 1
    for (int it = 0; it < NIT; ++it) {
        const int s = it & 3;
        // complete stage it: pending = min(3, NIT-it) -> wait pending-1
        if (it <= NIT - 3)
            asm volatile("cp.async.wait_group 2;\n" ::: "memory");
        else if (it == NIT - 2)
            asm volatile("cp.async.wait_group 1;\n" ::: "memory");
        else
            asm volatile("cp.async.wait_group 0;\n" ::: "memory");
        __syncthreads();

        if (it + 3 < NIT) {
            load_stage(it + 3, (it + 3) & 3);
            asm volatile("cp.async.commit_group;\n" ::: "memory");
        }

        const unsigned aB = smemBase + s * STGB;
        const unsigned bB = aB + ASTG;
#pragma unroll
        for (int step = 0; step < 2; ++step) {
            const int kb = step * 32;
            uint32_t af[4][4];
#pragma unroll
            for (int mi = 0; mi < 4; ++mi)
                ldsm4(af[mi][0], af[mi][1], af[mi][2], af[mi][3],
                      aB + (unsigned)((aRowL + mi * 16) * 80 + kb + aKoffL));
            uint32_t bf[4][2];
#pragma unroll
            for (int ni2 = 0; ni2 < 2; ++ni2)
                ldsm4(bf[2 * ni2][0], bf[2 * ni2][1], bf[2 * ni2 + 1][0], bf[2 * ni2 + 1][1],
                      bB + (unsigned)((bRowL + ni2 * 16) * 80 + kb + bKoffL));
#pragma unroll
            for (int mi = 0; mi < 4; ++mi)
#pragma unroll
                for (int ni = 0; ni < 4; ++ni) {
                    asm volatile(
                        "mma.sync.aligned.m16n8k16.row.col.f32.f16.f16.f32 "
                        "{%0,%1,%2,%3}, {%4,%5,%6,%7}, {%8,%9}, {%0,%1,%2,%3};"
                        : "+f"(acc[mi][ni][0]), "+f"(acc[mi][ni][1]),
                          "+f"(acc[mi][ni][2]), "+f"(acc[mi][ni][3])
                        : "r"(af[mi][0]), "r"(af[mi][1]),
                          "r"(af[mi][2]), "r"(af[mi][3]),
                          "r"(bf[ni][0]), "r"(bf[ni][1]));
                }
        }
    }

    // epilogue: add bias, store NCHW f32 to g_a
#pragma unroll
    for (int mi = 0; mi < 4; ++mi) {
#pragma unroll
        for (int ni = 0; ni < 4; ++ni) {
            const int n = n0 + wn * 32 + ni * 8 + 2 * t4;
            const float b0v = bias[n];
            const float b1v = bias[n + 1];
#pragma unroll
            for (int rr = 0; rr < 2; ++rr) {
                const int m = wm * 64 + mi * 16 + g4 + rr * 8;
                const int h = h0 + (m >> 5);
                const int w = m & 31;
                size_t base = ((size_t)(bimg * 384 + n) * 32 + h) * 32 + w;
                g_a[base]        = acc[mi][ni][rr * 2 + 0] + b0v;
                g_a[base + 1024] = acc[mi][ni][rr * 2 + 1] + b1v;
            }
        }
    }
}

// ---------------------------------------------------------------------------
// affine1: block per (b,h). Computes y2, writes out rows perm(192+c) (f32),
// stages y2 -> NHWC half for conv2's A path.
// ---------------------------------------------------------------------------
__global__ __launch_bounds__(256) void affine1_kernel(const float* __restrict__ x,
                                                      const float* __restrict__ act_offset,
                                                      float* __restrict__ outp) {
    __shared__ __half yt[32][194];
    const int b = blockIdx.x >> 5, h = blockIdx.x & 31;

    for (int idx = threadIdx.x; idx < 192 * 32; idx += 256) {
        const int c = idx >> 5, w = idx & 31;
        const int hw = h * 32 + w;
        const float lo = g_a[(((size_t)(b * 384 + c)) << 10) + hw];
        const float hi = g_a[(((size_t)(b * 384 + c + 192)) << 10) + hw];
        const int cc = c >> 2, ii = (c >> 1) & 1, jj = c & 1;
        const float xd = x[(((size_t)b * 96 + 48 + cc) * 64 + 2 * h + ii) * 64 + 2 * w + jj];
        const float y = xd * expf(2.0f * tanhf(0.2f * lo)) + hi;
        yt[w][c] = __float2half(y);
        const int p = 192 + c;
        outp[(((size_t)(b * 384 + g_invperm[p])) << 10) + hw] = y * g_scale[p] + act_offset[p];
    }
    __syncthreads();
    for (int idx = threadIdx.x; idx < 32 * 96; idx += 256) {
        const int w = idx / 96;
        const int c2 = (idx % 96) * 2;
        *(__half2*)&g_y2h[(((size_t)(b * 32 + h) * 32) + w) * 192 + c2] =
            *(const __half2*)&yt[w][c2];
    }
}

// affine2: y1 from down(x1)+a2 -> out rows perm(c)
__global__ __launch_bounds__(256) void affine2_kernel(const float* __restrict__ x,
                                                      const float* __restrict__ act_offset,
                                                      float* __restrict__ outp) {
    int idx = blockIdx.x * 256 + threadIdx.x;
    if (idx >= 32 * 96 * 1024) return;
    const int hw = idx & 1023;
    const int t = idx >> 10;
    const int cp = t % 96;
    const int b = t / 96;
    const int h = hw >> 5, w = hw & 31;
    const int c0 = 2 * cp;
    const int cc = cp >> 1, ii = cp & 1;

    const float lo0 = g_a[(((size_t)(b * 384 + c0)) << 10) + hw];
    const float lo1 = g_a[(((size_t)(b * 384 + c0 + 1)) << 10) + hw];
    const float hi0 = g_a[(((size_t)(b * 384 + c0 + 192)) << 10) + hw];
    const float hi1 = g_a[(((size_t)(b * 384 + c0 + 193)) << 10) + hw];
    const float2 xd = *(const float2*)&x[(((size_t)b * 96 + cc) * 64 + 2 * h + ii) * 64 + 2 * w];

    const float y0 = xd.x * expf(2.0f * tanhf(0.2f * lo0)) + hi0;
    const float y1 = xd.y * expf(2.0f * tanhf(0.2f * lo1)) + hi1;

    outp[(((size_t)(b * 384 + g_invperm[c0])) << 10) + hw]     = y0 * g_scale[c0] + act_offset[c0];
    outp[(((size_t)(b * 384 + g_invperm[c0 + 1])) << 10) + hw] = y1 * g_scale[c0 + 1] + act_offset[c0 + 1];
}

// ---------------------------------------------------------------------------
extern "C" void kernel_launch(void* const* d_in, const int* in_sizes, int n_in,
                              void* d_out, int out_size) {
    const float* x          = (const float*)d_in[0];
    const float* w_hi       = (const float*)d_in[1];
    const float* b_hi       = (const float*)d_in[2];
    const float* w_lo       = (const float*)d_in[3];
    const float* b_lo       = (const float*)d_in[4];
    const float* act_norm   = (const float*)d_in[5];
    const float* act_offset = (const float*)d_in[6];
    const float* perm_w     = (const float*)d_in[7];
    float* out = (float*)d_out;

    const int SMEM_DYN = 4 * STGB;   // 81920 B

    cudaFuncSetAttribute(conv_gemm<48, 64, 2, 64, 48, 1>,
                         cudaFuncAttributeMaxDynamicSharedMemorySize, SMEM_DYN);
    cudaFuncSetAttribute(conv_gemm<192, 192, 1, 32, 192, 2>,
                         cudaFuncAttributeMaxDynamicSharedMemorySize, SMEM_DYN);

    prep_kernel<<<1, 384>>>(perm_w, act_norm);
    pack_kernel<<<(9 * 2 * 384 * 32 + 255) / 256, 256>>>(w_hi, 48, 2, 0);
    pack_kernel<<<(9 * 6 * 384 * 32 + 255) / 256, 256>>>(w_lo, 192, 6, 1);
    x2h_kernel<<<32 * 64, 256>>>(x);

    conv_gemm<48, 64, 2, 64, 48, 1><<<dim3(256, 3), 256, SMEM_DYN>>>(b_hi);

    affine1_kernel<<<32 * 32, 256>>>(x, act_offset, out);

    conv_gemm<192, 192, 1, 32, 192, 2><<<dim3(256, 3), 256, SMEM_DYN>>>(b_lo);

    {
        int total = 32 * 96 * 1024;
        affine2_kernel<<<(total + 255) / 256, 256>>>(x, act_offset, out);
    }
}

// round 10
// speedup vs baseline: 1.9156x; 1.1355x over previous
#include <cuda_runtime.h>
#include <cuda_fp16.h>
#include <math.h>
#include <stdint.h>

// ---------------------------------------------------------------------------
// AIO_DownsampleCouplingBlock — Round 10: affines fused into conv epilogues.
// Weight N-dim repacked so each 128-col N-block = 64 lo + 64 paired hi
// channels -> (lo, hi) pair lives in one thread's registers. g_a eliminated.
// ---------------------------------------------------------------------------

__device__ __align__(16) __half g_xh[32 * 64 * 64 * 48];    // x1 NHWC half
__device__ __align__(16) __half g_y2h[32 * 32 * 32 * 192];  // y2 NHWC half
__device__ __align__(16) __half g_wp1[18 * 384 * 32];       // conv1 w [st][nn][k]
__device__ __align__(16) __half g_wp2[54 * 384 * 32];       // conv2 w [st][nn][k]
__device__ int   g_invperm[384];
__device__ float g_scale[384];

__device__ __forceinline__ void cp_async16(unsigned dst, const void* src) {
    asm volatile("cp.async.cg.shared.global [%0], [%1], 16;\n"
                 :: "r"(dst), "l"(src));
}
__device__ __forceinline__ void cp_async16z(unsigned dst, const void* src, int sz) {
    asm volatile("cp.async.cg.shared.global [%0], [%1], 16, %2;\n"
                 :: "r"(dst), "l"(src), "r"(sz));
}
__device__ __forceinline__ void ldsm4(uint32_t& r0, uint32_t& r1,
                                      uint32_t& r2, uint32_t& r3, unsigned addr) {
    asm volatile("ldmatrix.sync.aligned.m8n8.x4.shared.b16 {%0,%1,%2,%3}, [%4];"
                 : "=r"(r0), "=r"(r1), "=r"(r2), "=r"(r3) : "r"(addr));
}

// ---------------------------------------------------------------------------
__global__ void prep_kernel(const float* __restrict__ perm_w,
                            const float* __restrict__ act_norm) {
    int p = threadIdx.x;
    if (p < 384) {
        int o_found = 0;
        for (int o = 0; o < 384; ++o)
            if (perm_w[o * 384 + p] > 0.5f) o_found = o;
        g_invperm[p] = o_found;
        g_scale[p] = 0.2f * log1pf(expf(0.5f * act_norm[p]));
    }
}

// pack OIHW w[n,c,kh,kw] -> dst[st][nn(384)][k(32)] half, st = tap*CH + cblk
// nn remap: block y (nn>>7), row r (nn&127):
//   r < 64 : n = y*64 + r          (lo channel)
//   r >= 64: n = 192 + y*64 + r-64 (paired hi channel)
__global__ void pack_kernel(const float* __restrict__ w, int cin, int CH, int which) {
    __half* dst = which ? ((__half*)g_wp2) : ((__half*)g_wp1);
    int idx = blockIdx.x * 256 + threadIdx.x;
    int total = 9 * CH * 384 * 32;
    if (idx >= total) return;
    int k = idx & 31;
    int nn = (idx >> 5) % 384;
    int st = idx / (384 * 32);
    int yb = nn >> 7, r = nn & 127;
    int n = (r < 64) ? (yb * 64 + r) : (192 + yb * 64 + (r - 64));
    int tap = st / CH;
    int c = (st % CH) * 32 + k;
    float v = (c < cin) ? w[(n * cin + c) * 9 + tap] : 0.0f;
    dst[idx] = __float2half(v);
}

// x (NCHW f32, first 48 channels) -> g_xh (NHWC half), half2 stores
__global__ __launch_bounds__(256) void x2h_kernel(const float* __restrict__ x) {
    __shared__ float tile[48][65];
    const int b = blockIdx.x >> 6, h = blockIdx.x & 63;
    for (int idx = threadIdx.x; idx < 48 * 64; idx += 256) {
        const int c = idx >> 6, w = idx & 63;
        tile[c][w] = x[(((size_t)b * 96 + c) * 64 + h) * 64 + w];
    }
    __syncthreads();
    for (int idx = threadIdx.x; idx < 64 * 24; idx += 256) {
        const int w = idx / 24, cp = idx % 24;
        __half2 v = __floats2half2_rn(tile[2 * cp][w], tile[2 * cp + 1][w]);
        *(__half2*)&g_xh[(((size_t)b * 64 + h) * 64 + w) * 48 + 2 * cp] = v;
    }
}

// ---------------------------------------------------------------------------
// fused implicit-GEMM conv + affine epilogue.
// fp16 m16n8k16 mma.sync + ldmatrix, 4-stage cp.async, BK=32.
// M=32768 px, N-blocks: y in {0,1,2}, each = 64 lo + 64 paired hi channels.
// Warp wn: ni 0,1 -> lo rows wn*16+ni*8 ; ni 2,3 -> hi rows 64+wn*16+(ni-2)*8.
// WHICH=1 (conv1): epilogue = affine1 -> g_y2h + out rows invperm[192+c]
// WHICH=2 (conv2): epilogue = affine2 -> out rows invperm[c]
// ---------------------------------------------------------------------------
#define ASTG 10240          // 128*80 bytes
#define STGB 20480          // A + B per stage

template <int CIN, int CINP, int STRIDE, int HIN, int CTOT, int WHICH>
__global__ __launch_bounds__(256, 2) void conv_fused(
    const float* __restrict__ x,
    const float* __restrict__ bias,
    const float* __restrict__ act_offset,
    float* __restrict__ outp) {
    extern __shared__ __align__(16) char smem[];

    const __half* inp = (WHICH == 1) ? (const __half*)g_xh : (const __half*)g_y2h;
    const __half* wp  = (WHICH == 1) ? (const __half*)g_wp1 : (const __half*)g_wp2;
    constexpr int XOFF  = (WHICH == 1) ? 48 : 0;
    constexpr int PBASE = (WHICH == 1) ? 192 : 0;

    const int tid  = threadIdx.x;
    const int lane = tid & 31;
    const int warp = tid >> 5;
    const int wm = warp >> 2;
    const int wn = warp & 3;
    const int g4 = lane >> 2;
    const int t4 = lane & 3;

    const int bm   = blockIdx.x;
    const int bimg = bm >> 3;
    const int h0   = (bm & 7) * 4;
    const int yb   = blockIdx.y;
    const int n0   = yb * 128;

    constexpr int CH  = CINP / 32;
    constexpr int NIT = 9 * CH;

    const unsigned smemBase = (unsigned)__cvta_generic_to_shared(smem);
    const int aRowL = wm * 64 + (lane & 15);
    const int aKoffL = (lane >> 4) << 4;
    const int bRow0 = wn * 16 + ((lane >> 4) << 3) + (lane & 7);
    const int bKoffL = ((lane >> 3) & 1) << 4;

    float acc[4][4][4];
#pragma unroll
    for (int i = 0; i < 4; i++)
#pragma unroll
        for (int j = 0; j < 4; j++)
#pragma unroll
            for (int k = 0; k < 4; k++) acc[i][j][k] = 0.f;

    auto load_stage = [&](int it, int s) {
        const int tap = it / CH;
        const int c0  = (it - tap * CH) * 32;
        const int dh = tap / 3 - 1;
        const int dw = tap % 3 - 1;
        const unsigned aB = smemBase + s * STGB;
        const unsigned bB = aB + ASTG;
#pragma unroll
        for (int p = 0; p < 2; ++p) {
            const int task = tid + 256 * p;
            const int row = task >> 2;
            const int ch  = task & 3;
            const int h = h0 + (row >> 5);
            const int w = row & 31;
            const int ih = h * STRIDE + dh;
            const int iw = w * STRIDE + dw;
            const bool ok = (ih >= 0) && (ih < HIN) && (iw >= 0) && (iw < HIN)
                            && (c0 + ch * 8 < CIN);
            const __half* src = ok
                ? inp + ((size_t)(bimg * HIN + ih) * HIN + iw) * CTOT + c0 + ch * 8
                : inp;
            cp_async16z(aB + (unsigned)(row * 80 + ch * 16), src, ok ? 16 : 0);
        }
        const __half* wsrc = wp + (size_t)it * (384 * 32) + (size_t)n0 * 32;
#pragma unroll
        for (int p = 0; p < 2; ++p) {
            const int task = tid + 256 * p;
            const int row = task >> 2;
            const int ch  = task & 3;
            cp_async16(bB + (unsigned)(row * 80 + ch * 16), wsrc + row * 32 + ch * 8);
        }
    };

    load_stage(0, 0);
    asm volatile("cp.async.commit_group;\n" ::: "memory");
    load_stage(1, 1);
    asm volatile("cp.async.commit_group;\n" ::: "memory");
    load_stage(2, 2);
    asm volatile("cp.async.commit_group;\n" ::: "memory");

#pragma unroll 1
    for (int it = 0; it < NIT; ++it) {
        const int s = it & 3;
        if (it <= NIT - 3)
            asm volatile("cp.async.wait_group 2;\n" ::: "memory");
        else if (it == NIT - 2)
            asm volatile("cp.async.wait_group 1;\n" ::: "memory");
        else
            asm volatile("cp.async.wait_group 0;\n" ::: "memory");
        __syncthreads();

        if (it + 3 < NIT) {
            load_stage(it + 3, (it + 3) & 3);
            asm volatile("cp.async.commit_group;\n" ::: "memory");
        }

        const unsigned aB = smemBase + s * STGB;
        const unsigned bB = aB + ASTG;
#pragma unroll
        for (int step = 0; step < 2; ++step) {
            const int kb = step * 32;
            uint32_t af[4][4];
#pragma unroll
            for (int mi = 0; mi < 4; ++mi)
                ldsm4(af[mi][0], af[mi][1], af[mi][2], af[mi][3],
                      aB + (unsigned)((aRowL + mi * 16) * 80 + kb + aKoffL));
            uint32_t bf[4][2];
            ldsm4(bf[0][0], bf[0][1], bf[1][0], bf[1][1],
                  bB + (unsigned)(bRow0 * 80 + kb + bKoffL));
            ldsm4(bf[2][0], bf[2][1], bf[3][0], bf[3][1],
                  bB + (unsigned)((bRow0 + 64) * 80 + kb + bKoffL));
#pragma unroll
            for (int mi = 0; mi < 4; ++mi)
#pragma unroll
                for (int ni = 0; ni < 4; ++ni) {
                    asm volatile(
                        "mma.sync.aligned.m16n8k16.row.col.f32.f16.f16.f32 "
                        "{%0,%1,%2,%3}, {%4,%5,%6,%7}, {%8,%9}, {%0,%1,%2,%3};"
                        : "+f"(acc[mi][ni][0]), "+f"(acc[mi][ni][1]),
                          "+f"(acc[mi][ni][2]), "+f"(acc[mi][ni][3])
                        : "r"(af[mi][0]), "r"(af[mi][1]),
                          "r"(af[mi][2]), "r"(af[mi][3]),
                          "r"(bf[ni][0]), "r"(bf[ni][1]));
                }
        }
    }

    // ---- fused affine epilogue -------------------------------------------
    // ni in {0,1}: lo channel c = yb*64 + wn*16 + ni*8 + 2*t4 (+0/1)
    // paired hi accumulator at ni+2 (channel c+192)
#pragma unroll
    for (int ni = 0; ni < 2; ++ni) {
        const int c = yb * 64 + wn * 16 + ni * 8 + 2 * t4;   // even
        const float bl0 = bias[c],        bl1 = bias[c + 1];
        const float bh0 = bias[c + 192],  bh1 = bias[c + 193];
        const int p0 = PBASE + c, p1 = PBASE + c + 1;
        const float sc0 = g_scale[p0], sc1 = g_scale[p1];
        const float ao0 = act_offset[p0], ao1 = act_offset[p1];
        const int o0 = g_invperm[p0], o1 = g_invperm[p1];
        const int cc = c >> 2, ii = (c >> 1) & 1;
        const float* xrowb = x + (((size_t)bimg * 96 + XOFF + cc) * 64 + ii) * 64;
#pragma unroll
        for (int mi = 0; mi < 4; ++mi) {
#pragma unroll
            for (int rr = 0; rr < 2; ++rr) {
                const int m = wm * 64 + mi * 16 + g4 + rr * 8;
                const int h = h0 + (m >> 5);
                const int w = m & 31;
                const float lo0 = acc[mi][ni][rr * 2 + 0] + bl0;
                const float lo1 = acc[mi][ni][rr * 2 + 1] + bl1;
                const float hi0 = acc[mi][ni + 2][rr * 2 + 0] + bh0;
                const float hi1 = acc[mi][ni + 2][rr * 2 + 1] + bh1;
                const float2 xd = *(const float2*)&xrowb[(size_t)(2 * h) * 64 + 2 * w];
                const float y0 = xd.x * expf(2.0f * tanhf(0.2f * lo0)) + hi0;
                const float y1 = xd.y * expf(2.0f * tanhf(0.2f * lo1)) + hi1;
                const int hw = h * 32 + w;
                if (WHICH == 1) {
                    *(__half2*)&g_y2h[(((size_t)(bimg * 32 + h) * 32) + w) * 192 + c] =
                        __floats2half2_rn(y0, y1);
                }
                outp[(((size_t)(bimg * 384 + o0)) << 10) + hw] = y0 * sc0 + ao0;
                outp[(((size_t)(bimg * 384 + o1)) << 10) + hw] = y1 * sc1 + ao1;
            }
        }
    }
}

// ---------------------------------------------------------------------------
extern "C" void kernel_launch(void* const* d_in, const int* in_sizes, int n_in,
                              void* d_out, int out_size) {
    const float* x          = (const float*)d_in[0];
    const float* w_hi       = (const float*)d_in[1];
    const float* b_hi       = (const float*)d_in[2];
    const float* w_lo       = (const float*)d_in[3];
    const float* b_lo       = (const float*)d_in[4];
    const float* act_norm   = (const float*)d_in[5];
    const float* act_offset = (const float*)d_in[6];
    const float* perm_w     = (const float*)d_in[7];
    float* out = (float*)d_out;

    const int SMEM_DYN = 4 * STGB;   // 81920 B

    cudaFuncSetAttribute(conv_fused<48, 64, 2, 64, 48, 1>,
                         cudaFuncAttributeMaxDynamicSharedMemorySize, SMEM_DYN);
    cudaFuncSetAttribute(conv_fused<192, 192, 1, 32, 192, 2>,
                         cudaFuncAttributeMaxDynamicSharedMemorySize, SMEM_DYN);

    prep_kernel<<<1, 384>>>(perm_w, act_norm);
    pack_kernel<<<(9 * 2 * 384 * 32 + 255) / 256, 256>>>(w_hi, 48, 2, 0);
    pack_kernel<<<(9 * 6 * 384 * 32 + 255) / 256, 256>>>(w_lo, 192, 6, 1);
    x2h_kernel<<<32 * 64, 256>>>(x);

    conv_fused<48, 64, 2, 64, 48, 1><<<dim3(256, 3), 256, SMEM_DYN>>>(
        x, b_hi, act_offset, out);

    conv_fused<192, 192, 1, 32, 192, 2><<<dim3(256, 3), 256, SMEM_DYN>>>(
        x, b_lo, act_offset, out);
}

// round 11
// speedup vs baseline: 2.0450x; 1.0675x over previous
#include <cuda_runtime.h>
#include <cuda_fp16.h>
#include <math.h>
#include <stdint.h>

// ---------------------------------------------------------------------------
// AIO_DownsampleCouplingBlock — Round 11: exact-K stages (BK=48 conv1, BK=64
// conv2), halved barrier counts, fused affine epilogues (from round 10).
// ---------------------------------------------------------------------------

__device__ __align__(16) __half g_xh[32 * 64 * 64 * 48];    // x1 NHWC half
__device__ __align__(16) __half g_y2h[32 * 32 * 32 * 192];  // y2 NHWC half
__device__ __align__(16) __half g_wp1[9 * 384 * 48];        // conv1 w [st][nn][48]
__device__ __align__(16) __half g_wp2[27 * 384 * 64];       // conv2 w [st][nn][64]
__device__ int   g_invperm[384];
__device__ float g_scale[384];

__device__ __forceinline__ void cp_async16(unsigned dst, const void* src) {
    asm volatile("cp.async.cg.shared.global [%0], [%1], 16;\n"
                 :: "r"(dst), "l"(src));
}
__device__ __forceinline__ void cp_async16z(unsigned dst, const void* src, int sz) {
    asm volatile("cp.async.cg.shared.global [%0], [%1], 16, %2;\n"
                 :: "r"(dst), "l"(src), "r"(sz));
}
__device__ __forceinline__ void ldsm4(uint32_t& r0, uint32_t& r1,
                                      uint32_t& r2, uint32_t& r3, unsigned addr) {
    asm volatile("ldmatrix.sync.aligned.m8n8.x4.shared.b16 {%0,%1,%2,%3}, [%4];"
                 : "=r"(r0), "=r"(r1), "=r"(r2), "=r"(r3) : "r"(addr));
}

// ---------------------------------------------------------------------------
__global__ void prep_kernel(const float* __restrict__ perm_w,
                            const float* __restrict__ act_norm) {
    int p = threadIdx.x;
    if (p < 384) {
        int o_found = 0;
        for (int o = 0; o < 384; ++o)
            if (perm_w[o * 384 + p] > 0.5f) o_found = o;
        g_invperm[p] = o_found;
        g_scale[p] = 0.2f * log1pf(expf(0.5f * act_norm[p]));
    }
}

// nn remap: block y (nn>>7), row r (nn&127):
//   r < 64 : n = y*64 + r ; r >= 64: n = 192 + y*64 + (r-64)
__device__ __forceinline__ int nn_to_n(int nn) {
    int yb = nn >> 7, r = nn & 127;
    return (r < 64) ? (yb * 64 + r) : (192 + yb * 64 + (r - 64));
}

// both weight packs in one launch: dst[st][nn(384)][k(KB)], exact K (no pad)
__global__ void pack_all_kernel(const float* __restrict__ w_hi,
                                const float* __restrict__ w_lo) {
    const int T1 = 9 * 384 * 48;
    const int T2 = 27 * 384 * 64;
    int idx = blockIdx.x * 256 + threadIdx.x;
    if (idx < T1) {
        int k = idx % 48;
        int nn = (idx / 48) % 384;
        int st = idx / (48 * 384);        // = tap
        int n = nn_to_n(nn);
        g_wp1[idx] = __float2half(w_hi[(n * 48 + k) * 9 + st]);
    } else if (idx < T1 + T2) {
        int j = idx - T1;
        int k = j % 64;
        int nn = (j / 64) % 384;
        int st = j / (64 * 384);          // tap = st/3, cblk = st%3
        int n = nn_to_n(nn);
        int tap = st / 3;
        int c = (st % 3) * 64 + k;
        g_wp2[j] = __float2half(w_lo[(n * 192 + c) * 9 + tap]);
    }
}

// x (NCHW f32, first 48 channels) -> g_xh (NHWC half), half2 stores
__global__ __launch_bounds__(256) void x2h_kernel(const float* __restrict__ x) {
    __shared__ float tile[48][65];
    const int b = blockIdx.x >> 6, h = blockIdx.x & 63;
    for (int idx = threadIdx.x; idx < 48 * 64; idx += 256) {
        const int c = idx >> 6, w = idx & 63;
        tile[c][w] = x[(((size_t)b * 96 + c) * 64 + h) * 64 + w];
    }
    __syncthreads();
    for (int idx = threadIdx.x; idx < 64 * 24; idx += 256) {
        const int w = idx / 24, cp = idx % 24;
        __half2 v = __floats2half2_rn(tile[2 * cp][w], tile[2 * cp + 1][w]);
        *(__half2*)&g_xh[(((size_t)b * 64 + h) * 64 + w) * 48 + 2 * cp] = v;
    }
}

// ---------------------------------------------------------------------------
// fused implicit-GEMM conv + affine epilogue (fp16 m16n8k16 + ldmatrix).
// KB = K-depth per stage (halves), NST = pipeline stages, CH = K-blocks/tap.
// A smem [m(128)][KB halves] rows padded +16B; B smem [nn(128)][KB] same.
// 256 thr / 8 warps, warp grid 2(M) x 4(N), warp tile 64x32.
// N-block yb: 64 lo + 64 paired hi channels; epilogue does the affine.
// ---------------------------------------------------------------------------
template <int KB, int NST, int CH, int STRIDE, int HIN, int CTOT, int WHICH>
__global__ __launch_bounds__(256, 2) void conv_fused(
    const float* __restrict__ x,
    const float* __restrict__ bias,
    const float* __restrict__ act_offset,
    float* __restrict__ outp) {
    extern __shared__ __align__(16) char smem[];

    constexpr int ROWB   = KB * 2 + 16;      // bytes per smem row
    constexpr int ASTG   = 128 * ROWB;
    constexpr int STGB   = 2 * ASTG;
    constexpr int KSTEPS = KB / 16;
    constexpr int CHK    = KB / 8;           // 16B chunks per row
    constexpr int TPT    = CHK / 2;          // tasks per thread (128*CHK/256)
    constexpr int NIT    = 9 * CH;

    const __half* inp = (WHICH == 1) ? (const __half*)g_xh : (const __half*)g_y2h;
    const __half* wp  = (WHICH == 1) ? (const __half*)g_wp1 : (const __half*)g_wp2;
    constexpr int XOFF  = (WHICH == 1) ? 48 : 0;
    constexpr int PBASE = (WHICH == 1) ? 192 : 0;

    const int tid  = threadIdx.x;
    const int lane = tid & 31;
    const int warp = tid >> 5;
    const int wm = warp >> 2;
    const int wn = warp & 3;
    const int g4 = lane >> 2;
    const int t4 = lane & 3;

    const int bm   = blockIdx.x;
    const int bimg = bm >> 3;
    const int h0   = (bm & 7) * 4;
    const int yb   = blockIdx.y;
    const int n0   = yb * 128;

    const unsigned smemBase = (unsigned)__cvta_generic_to_shared(smem);
    const int aRowL = wm * 64 + (lane & 15);
    const int aKoffL = (lane >> 4) << 4;
    const int bRow0 = wn * 16 + ((lane >> 4) << 3) + (lane & 7);
    const int bKoffL = ((lane >> 3) & 1) << 4;

    float acc[4][4][4];
#pragma unroll
    for (int i = 0; i < 4; i++)
#pragma unroll
        for (int j = 0; j < 4; j++)
#pragma unroll
            for (int k = 0; k < 4; k++) acc[i][j][k] = 0.f;

    auto load_stage = [&](int it, int s) {
        const int tap = it / CH;
        const int c0  = (it - tap * CH) * KB;
        const int dh = tap / 3 - 1;
        const int dw = tap % 3 - 1;
        const unsigned aB = smemBase + s * STGB;
        const unsigned bB = aB + ASTG;
#pragma unroll
        for (int p = 0; p < TPT; ++p) {
            const int task = tid + 256 * p;
            const int row = task / CHK;
            const int ch  = task - row * CHK;
            const int h = h0 + (row >> 5);
            const int w = row & 31;
            const int ih = h * STRIDE + dh;
            const int iw = w * STRIDE + dw;
            const bool ok = (ih >= 0) && (ih < HIN) && (iw >= 0) && (iw < HIN);
            const __half* src = ok
                ? inp + ((size_t)(bimg * HIN + ih) * HIN + iw) * CTOT + c0 + ch * 8
                : inp;
            cp_async16z(aB + (unsigned)(row * ROWB + ch * 16), src, ok ? 16 : 0);
        }
        const __half* wsrc = wp + (size_t)it * (384 * KB) + (size_t)n0 * KB;
#pragma unroll
        for (int p = 0; p < TPT; ++p) {
            const int task = tid + 256 * p;
            const int row = task / CHK;
            const int ch  = task - row * CHK;
            cp_async16(bB + (unsigned)(row * ROWB + ch * 16), wsrc + row * KB + ch * 8);
        }
    };

    // prologue: NST-1 stages in flight
#pragma unroll
    for (int ps = 0; ps < NST - 1; ++ps) {
        load_stage(ps, ps);
        asm volatile("cp.async.commit_group;\n" ::: "memory");
    }

    int s = 0;
#pragma unroll 1
    for (int it = 0; it < NIT; ++it) {
        // wait for stage it: pending after = min(NST-2, NIT-1-it)
        if (NST == 4) {
            if (it <= NIT - 3)
                asm volatile("cp.async.wait_group 2;\n" ::: "memory");
            else if (it == NIT - 2)
                asm volatile("cp.async.wait_group 1;\n" ::: "memory");
            else
                asm volatile("cp.async.wait_group 0;\n" ::: "memory");
        } else {  // NST == 3
            if (it <= NIT - 2)
                asm volatile("cp.async.wait_group 1;\n" ::: "memory");
            else
                asm volatile("cp.async.wait_group 0;\n" ::: "memory");
        }
        __syncthreads();

        if (it + NST - 1 < NIT) {
            int sw = s - 1; if (sw < 0) sw += NST;   // == (it+NST-1) % NST
            load_stage(it + NST - 1, sw);
            asm volatile("cp.async.commit_group;\n" ::: "memory");
        }

        const unsigned aB = smemBase + s * STGB;
        const unsigned bB = aB + ASTG;
#pragma unroll
        for (int step = 0; step < KSTEPS; ++step) {
            const int kb = step * 32;
            uint32_t af[4][4];
#pragma unroll
            for (int mi = 0; mi < 4; ++mi)
                ldsm4(af[mi][0], af[mi][1], af[mi][2], af[mi][3],
                      aB + (unsigned)((aRowL + mi * 16) * ROWB + kb + aKoffL));
            uint32_t bf[4][2];
            ldsm4(bf[0][0], bf[0][1], bf[1][0], bf[1][1],
                  bB + (unsigned)(bRow0 * ROWB + kb + bKoffL));
            ldsm4(bf[2][0], bf[2][1], bf[3][0], bf[3][1],
                  bB + (unsigned)((bRow0 + 64) * ROWB + kb + bKoffL));
#pragma unroll
            for (int mi = 0; mi < 4; ++mi)
#pragma unroll
                for (int ni = 0; ni < 4; ++ni) {
                    asm volatile(
                        "mma.sync.aligned.m16n8k16.row.col.f32.f16.f16.f32 "
                        "{%0,%1,%2,%3}, {%4,%5,%6,%7}, {%8,%9}, {%0,%1,%2,%3};"
                        : "+f"(acc[mi][ni][0]), "+f"(acc[mi][ni][1]),
                          "+f"(acc[mi][ni][2]), "+f"(acc[mi][ni][3])
                        : "r"(af[mi][0]), "r"(af[mi][1]),
                          "r"(af[mi][2]), "r"(af[mi][3]),
                          "r"(bf[ni][0]), "r"(bf[ni][1]));
                }
        }
        if (++s == NST) s = 0;
    }

    // ---- fused affine epilogue -------------------------------------------
#pragma unroll
    for (int ni = 0; ni < 2; ++ni) {
        const int c = yb * 64 + wn * 16 + ni * 8 + 2 * t4;   // even
        const float bl0 = bias[c],        bl1 = bias[c + 1];
        const float bh0 = bias[c + 192],  bh1 = bias[c + 193];
        const int p0 = PBASE + c, p1 = PBASE + c + 1;
        const float sc0 = g_scale[p0], sc1 = g_scale[p1];
        const float ao0 = act_offset[p0], ao1 = act_offset[p1];
        const int o0 = g_invperm[p0], o1 = g_invperm[p1];
        const int cc = c >> 2, ii = (c >> 1) & 1;
        const float* xrowb = x + (((size_t)bimg * 96 + XOFF + cc) * 64 + ii) * 64;
#pragma unroll
        for (int mi = 0; mi < 4; ++mi) {
#pragma unroll
            for (int rr = 0; rr < 2; ++rr) {
                const int m = wm * 64 + mi * 16 + g4 + rr * 8;
                const int h = h0 + (m >> 5);
                const int w = m & 31;
                const float lo0 = acc[mi][ni][rr * 2 + 0] + bl0;
                const float lo1 = acc[mi][ni][rr * 2 + 1] + bl1;
                const float hi0 = acc[mi][ni + 2][rr * 2 + 0] + bh0;
                const float hi1 = acc[mi][ni + 2][rr * 2 + 1] + bh1;
                const float2 xd = *(const float2*)&xrowb[(size_t)(2 * h) * 64 + 2 * w];
                const float y0 = xd.x * expf(2.0f * tanhf(0.2f * lo0)) + hi0;
                const float y1 = xd.y * expf(2.0f * tanhf(0.2f * lo1)) + hi1;
                const int hw = h * 32 + w;
                if (WHICH == 1) {
                    *(__half2*)&g_y2h[(((size_t)(bimg * 32 + h) * 32) + w) * 192 + c] =
                        __floats2half2_rn(y0, y1);
                }
                outp[(((size_t)(bimg * 384 + o0)) << 10) + hw] = y0 * sc0 + ao0;
                outp[(((size_t)(bimg * 384 + o1)) << 10) + hw] = y1 * sc1 + ao1;
            }
        }
    }
}

// ---------------------------------------------------------------------------
extern "C" void kernel_launch(void* const* d_in, const int* in_sizes, int n_in,
                              void* d_out, int out_size) {
    const float* x          = (const float*)d_in[0];
    const float* w_hi       = (const float*)d_in[1];
    const float* b_hi       = (const float*)d_in[2];
    const float* w_lo       = (const float*)d_in[3];
    const float* b_lo       = (const float*)d_in[4];
    const float* act_norm   = (const float*)d_in[5];
    const float* act_offset = (const float*)d_in[6];
    const float* perm_w     = (const float*)d_in[7];
    float* out = (float*)d_out;

    // conv1: KB=48, NST=4 -> stage 28,672 B, total 114,688 B
    // conv2: KB=64, NST=3 -> stage 36,864 B, total 110,592 B
    const int SMEM1 = 4 * 2 * 128 * (48 * 2 + 16);
    const int SMEM2 = 3 * 2 * 128 * (64 * 2 + 16);

    cudaFuncSetAttribute(conv_fused<48, 4, 1, 2, 64, 48, 1>,
                         cudaFuncAttributeMaxDynamicSharedMemorySize, SMEM1);
    cudaFuncSetAttribute(conv_fused<64, 3, 3, 1, 32, 192, 2>,
                         cudaFuncAttributeMaxDynamicSharedMemorySize, SMEM2);

    prep_kernel<<<1, 384>>>(perm_w, act_norm);
    {
        int total = 9 * 384 * 48 + 27 * 384 * 64;
        pack_all_kernel<<<(total + 255) / 256, 256>>>(w_hi, w_lo);
    }
    x2h_kernel<<<32 * 64, 256>>>(x);

    conv_fused<48, 4, 1, 2, 64, 48, 1><<<dim3(256, 3), 256, SMEM1>>>(
        x, b_hi, act_offset, out);

    conv_fused<64, 3, 3, 1, 32, 192, 2><<<dim3(256, 3), 256, SMEM2>>>(
        x, b_lo, act_offset, out);
}